// round 2
// baseline (speedup 1.0000x reference)
#include <cuda_runtime.h>
#include <math.h>

#define HW    4096
#define CIN   512
#define COUT  256
#define BATCH 32

// ---------------- device scratch (no allocations allowed) ----------------
__device__ float g_g[BATCH * CIN];       // sum_hw feats*preds
__device__ float g_predsum[BATCH];       // sum_hw preds
__device__ float g_pooled[BATCH * COUT]; // pooled [B, C]
__device__ float g_mem[BATCH * COUT];    // codebook (ptr <= B = 32 rows ever used)
__device__ int   g_ptr;

__device__ __forceinline__ float warp_sum(float v) {
#pragma unroll
    for (int o = 16; o; o >>= 1) v += __shfl_down_sync(0xffffffffu, v, o);
    return v;
}

// ---------------- Kernel A: g[b,c] = sum_hw feats[b,c,hw]*preds[b,hw] ----
__global__ void gk_kernel(const float* __restrict__ feats,
                          const float* __restrict__ preds) {
    int c = blockIdx.x, b = blockIdx.y;
    const float* f  = feats + ((size_t)b * CIN + c) * HW;
    const float* pr = preds + (size_t)b * HW;
    int t = threadIdx.x;
    float s = 0.f;
#pragma unroll
    for (int i = t * 4; i < HW; i += 1024) {
        float4 fv = *(const float4*)(f + i);
        float4 pv = *(const float4*)(pr + i);
        s += fv.x * pv.x + fv.y * pv.y + fv.z * pv.z + fv.w * pv.w;
    }
    s = warp_sum(s);
    __shared__ float red[8];
    if ((t & 31) == 0) red[t >> 5] = s;
    __syncthreads();
    if (t == 0) {
        float tt = 0.f;
#pragma unroll
        for (int j = 0; j < 8; j++) tt += red[j];
        g_g[b * CIN + c] = tt;
    }
}

// ---------------- Kernel A2: predsum[b] ----------------------------------
__global__ void predsum_kernel(const float* __restrict__ preds) {
    int b = blockIdx.x;
    const float* pr = preds + (size_t)b * HW;
    int t = threadIdx.x;
    float s = 0.f;
    for (int i = t; i < HW; i += 256) s += pr[i];
    s = warp_sum(s);
    __shared__ float red[8];
    if ((t & 31) == 0) red[t >> 5] = s;
    __syncthreads();
    if (t == 0) {
        float tt = 0.f;
#pragma unroll
        for (int j = 0; j < 8; j++) tt += red[j];
        g_predsum[b] = tt;
    }
}

// ---------------- Kernel B: pooled[b,o] = (W@g + bias*predsum)/HW --------
__global__ void pooled_kernel(const float* __restrict__ W,
                              const float* __restrict__ bias) {
    __shared__ float gs[CIN];
    int b = blockIdx.x;
    int t = threadIdx.x;
    gs[t]       = g_g[b * CIN + t];
    gs[t + 256] = g_g[b * CIN + 256 + t];
    __syncthreads();
    const float* wr = W + (size_t)t * CIN;
    float s = 0.f;
#pragma unroll 8
    for (int c = 0; c < CIN; c++) s += wr[c] * gs[c];
    g_pooled[b * COUT + t] = (s + bias[t] * g_predsum[b]) * (1.0f / (float)HW);
}

// ---------------- Kernel C: sequential codebook scan (one block) ---------
__global__ void memscan_kernel(const int* __restrict__ epoch_p) {
    __shared__ float mem[32][COUT];
    __shared__ float x[COUT];
    __shared__ float sims[32];
    __shared__ float red[8];
    __shared__ float s_xnorm;
    __shared__ int   s_ptr, s_idx, s_ema;

    int t = threadIdx.x, lane = t & 31, w = t >> 5;
    if (t == 0) s_ptr = 0;
    float threshold = ((float)(*epoch_p) / 10.0f - 2.0f) * 0.4f / 13.0f + 0.3f;
    __syncthreads();

    for (int i = 0; i < BATCH; i++) {
        x[t] = g_pooled[i * COUT + t];
        __syncthreads();
        // ||x||
        float v = x[t] * x[t];
        v = warp_sum(v);
        if (lane == 0) red[w] = v;
        __syncthreads();
        if (t == 0) {
            float s = 0.f;
#pragma unroll
            for (int j = 0; j < 8; j++) s += red[j];
            s_xnorm = sqrtf(s);
        }
        __syncthreads();
        int ptr = s_ptr;
        float xnorm = s_xnorm;
        // cosine sims, one warp per slot (strided)
        for (int p = w; p < ptr; p += 8) {
            float dot = 0.f, nn = 0.f;
#pragma unroll
            for (int c = lane; c < COUT; c += 32) {
                float m = mem[p][c];
                dot += m * x[c];
                nn  += m * m;
            }
            dot = warp_sum(dot);
            nn  = warp_sum(nn);
            if (lane == 0) {
                float norm = sqrtf(nn);
                if (norm == 0.f) norm = 1.f;
                sims[p] = dot / (norm * xnorm);
            }
        }
        __syncthreads();
        if (t == 0) {
            int   idx  = 0;
            float best = -INFINITY;
            for (int p = 0; p < ptr; p++) {
                if (sims[p] > best) { best = sims[p]; idx = p; }  // first-max tie-break
            }
            int ema = (ptr > 0) && (best >= threshold);
            s_ema = ema;
            s_idx = ema ? idx : ptr;
            if (!ema) s_ptr = ptr + 1;
        }
        __syncthreads();
        if (s_ema) mem[s_idx][t] = mem[s_idx][t] * 0.9f + 0.1f * x[t];
        else       mem[s_idx][t] = x[t];
        __syncthreads();
    }
    int ptr = s_ptr;
    for (int p = 0; p < ptr; p++) g_mem[p * COUT + t] = mem[p][t];
    if (t == 0) g_ptr = ptr;
}

// ---------------- Kernel D: proj GEMM (128x128x8 SIMT fp32) --------------
// out[b, m, hw] = sum_c W[m,c]*feats[b,c,hw] + bias[m]   for m in [0,256)
__global__ __launch_bounds__(256, 2)
void proj_gemm(const float* __restrict__ feats,
               const float* __restrict__ W,
               const float* __restrict__ bias,
               float* __restrict__ out) {
    __shared__ float As[8][132];  // padded: conflict-free transpose stores
    __shared__ float Bs[8][128];

    int b  = blockIdx.z;
    int m0 = blockIdx.y * 128;
    int n0 = blockIdx.x * 128;
    const float* Bg = feats + (size_t)b * CIN * HW;
    float*       C  = out + (size_t)b * (2 * COUT) * HW;

    int t  = threadIdx.x;
    int tx = t & 15, ty = t >> 4;

    float acc[8][8];
#pragma unroll
    for (int i = 0; i < 8; i++)
#pragma unroll
        for (int j = 0; j < 8; j++) acc[i][j] = 0.f;

    int ar = t >> 1, akc = (t & 1) * 4;       // A tile load: 128x8
    int br = t >> 5, bc = (t & 31) * 4;       // B tile load: 8x128
    const float* Aptr = W + (size_t)(m0 + ar) * CIN + akc;
    const float* Bptr = Bg + (size_t)br * HW + n0 + bc;

    for (int k0 = 0; k0 < CIN; k0 += 8) {
        float4 av = *(const float4*)(Aptr + k0);
        float4 bv = *(const float4*)(Bptr + (size_t)k0 * HW);
        As[akc + 0][ar] = av.x;
        As[akc + 1][ar] = av.y;
        As[akc + 2][ar] = av.z;
        As[akc + 3][ar] = av.w;
        *(float4*)&Bs[br][bc] = bv;
        __syncthreads();
#pragma unroll
        for (int k = 0; k < 8; k++) {
            float a[8], bb[8];
            *(float4*)&a[0]  = *(const float4*)&As[k][ty * 8];
            *(float4*)&a[4]  = *(const float4*)&As[k][ty * 8 + 4];
            *(float4*)&bb[0] = *(const float4*)&Bs[k][tx * 8];
            *(float4*)&bb[4] = *(const float4*)&Bs[k][tx * 8 + 4];
#pragma unroll
            for (int i = 0; i < 8; i++)
#pragma unroll
                for (int j = 0; j < 8; j++) acc[i][j] += a[i] * bb[j];
        }
        __syncthreads();
    }
#pragma unroll
    for (int i = 0; i < 8; i++) {
        int m = m0 + ty * 8 + i;
        float bvs = bias[m];
        float4 o0, o1;
        o0.x = acc[i][0] + bvs; o0.y = acc[i][1] + bvs;
        o0.z = acc[i][2] + bvs; o0.w = acc[i][3] + bvs;
        o1.x = acc[i][4] + bvs; o1.y = acc[i][5] + bvs;
        o1.z = acc[i][6] + bvs; o1.w = acc[i][7] + bvs;
        float* Cp = C + (size_t)m * HW + n0 + tx * 8;
        *(float4*)Cp       = o0;
        *(float4*)(Cp + 4) = o1;
    }
}

// ---------------- Kernel E: memory cross-attention -----------------------
// per block: batch b, 128-wide L tile. logit -> softmax(valid slots) -> aug
__global__ __launch_bounds__(256)
void attn_kernel(float* __restrict__ out) {
    extern __shared__ float sm[];
    float* memS = sm;                                   // [32][256]
    float (*sbuf)[128] = (float(*)[128])(sm + 32 * COUT); // [32][128]

    int b  = blockIdx.y;
    int l0 = blockIdx.x * 128;
    int t  = threadIdx.x;
    int ptr = g_ptr;

    // load codebook, zero-fill invalid rows (so fixed-trip loops are safe)
    for (int idx = t; idx < 32 * COUT; idx += 256) {
        int p = idx >> 8;
        memS[idx] = (p < ptr) ? g_mem[idx] : 0.f;
    }
    const float* proj = out + (size_t)b * (2 * COUT) * HW;
    float*       aug  = out + (size_t)b * (2 * COUT) * HW + (size_t)COUT * HW;

    int tl = t & 31;   // l micro-tile (4 cols)
    int tp = t >> 5;   // p group (logit) / c group (aug)

    float acc[4][4];
#pragma unroll
    for (int i = 0; i < 4; i++)
#pragma unroll
        for (int j = 0; j < 4; j++) acc[i][j] = 0.f;
    __syncthreads();

    // logit[p][l] = sum_c memS[p][c] * proj[c][l0+l]
    for (int c0 = 0; c0 < COUT; c0 += 32) {
#pragma unroll
        for (int i = 0; i < 4; i++) {
            int idx = t + i * 256;
            int r   = idx >> 5;
            int cc  = (idx & 31) * 4;
            *(float4*)&sbuf[r][cc] =
                *(const float4*)(proj + (size_t)(c0 + r) * HW + l0 + cc);
        }
        __syncthreads();
#pragma unroll
        for (int cc = 0; cc < 32; cc++) {
            float4 xv = *(const float4*)&sbuf[cc][tl * 4];
#pragma unroll
            for (int i = 0; i < 4; i++) {
                float mv = memS[(tp * 4 + i) * COUT + c0 + cc];
                acc[i][0] += mv * xv.x;
                acc[i][1] += mv * xv.y;
                acc[i][2] += mv * xv.z;
                acc[i][3] += mv * xv.w;
            }
        }
        __syncthreads();
    }
    // logits -> shared
#pragma unroll
    for (int i = 0; i < 4; i++) {
        *(float4*)&sbuf[tp * 4 + i][tl * 4] =
            make_float4(acc[i][0], acc[i][1], acc[i][2], acc[i][3]);
    }
    __syncthreads();

    // softmax over valid slots, per l
    if (t < 128) {
        int l = t;
        float mx = -INFINITY;
        for (int p = 0; p < ptr; p++) mx = fmaxf(mx, sbuf[p][l]);
        float ssum = 0.f;
        for (int p = 0; p < ptr; p++) {
            float e = expf(sbuf[p][l] - mx);
            sbuf[p][l] = e;
            ssum += e;
        }
        float inv = 1.0f / ssum;
        for (int p = 0; p < ptr; p++) sbuf[p][l] *= inv;
    }
    __syncthreads();

    // aug[c][l] = sum_p attn[p][l] * memS[p][c]
    int cbase = tp * 32;
    for (int cb = 0; cb < 32; cb += 8) {
        float s[8][4];
#pragma unroll
        for (int q = 0; q < 8; q++)
#pragma unroll
            for (int j = 0; j < 4; j++) s[q][j] = 0.f;
        for (int p = 0; p < ptr; p++) {
            float4 xa = *(const float4*)&sbuf[p][tl * 4];
#pragma unroll
            for (int q = 0; q < 8; q++) {
                float mv = memS[p * COUT + cbase + cb + q];
                s[q][0] += mv * xa.x;
                s[q][1] += mv * xa.y;
                s[q][2] += mv * xa.z;
                s[q][3] += mv * xa.w;
            }
        }
#pragma unroll
        for (int q = 0; q < 8; q++) {
            *(float4*)(aug + (size_t)(cbase + cb + q) * HW + l0 + tl * 4) =
                make_float4(s[q][0], s[q][1], s[q][2], s[q][3]);
        }
    }
}

// ---------------- launch --------------------------------------------------
extern "C" void kernel_launch(void* const* d_in, const int* in_sizes, int n_in,
                              void* d_out, int out_size) {
    const float* feats = (const float*)d_in[0];
    const float* preds = (const float*)d_in[1];
    const float* W     = (const float*)d_in[2];
    const float* bias  = (const float*)d_in[3];
    const int*   epoch = (const int*)d_in[4];
    float* out = (float*)d_out;

    gk_kernel<<<dim3(CIN, BATCH), 256>>>(feats, preds);
    predsum_kernel<<<BATCH, 256>>>(preds);
    pooled_kernel<<<BATCH, 256>>>(W, bias);
    memscan_kernel<<<1, 256>>>(epoch);
    proj_gemm<<<dim3(HW / 128, COUT / 128, BATCH), 256>>>(feats, W, bias, out);
    attn_kernel<<<dim3(HW / 128, BATCH), 256, 49152>>>(out);
}

// round 4
// speedup vs baseline: 1.9814x; 1.9814x over previous
#include <cuda_runtime.h>
#include <math.h>
#include <stdint.h>

#define HW    4096
#define CIN   512
#define COUT  256
#define BATCH 32

// ---- proj GEMM tiling ----
#define BM 64
#define BN 256
#define BK 16
#define NKT (CIN / BK)          // 32 k-tiles
#define NSTB 4                  // B pipeline stages
#define A_STRIDE 516            // 64 rows x 516 floats (pad 4: conflict-free frags)
#define B_STRIDE 264            // 16 rows x 264 floats (pad 8: conflict-free frags)
#define A_BYTES (BM * A_STRIDE * 4)          // 132096
#define B_STAGE_BYTES (BK * B_STRIDE * 4)    // 16896
#define SMEM_TOTAL (A_BYTES + NSTB * B_STAGE_BYTES)  // 199680

// ---------------- device scratch ----------------
__device__ float g_g[BATCH * CIN];
__device__ float g_predsum[BATCH];
__device__ float g_pooled[BATCH * COUT];
__device__ float g_mem[BATCH * COUT];
__device__ int   g_ptr;

__device__ __forceinline__ float warp_sum(float v) {
#pragma unroll
    for (int o = 16; o; o >>= 1) v += __shfl_down_sync(0xffffffffu, v, o);
    return v;
}

__device__ __forceinline__ uint32_t smem_u32(const void* p) {
    uint32_t a;
    asm("{ .reg .u64 t; cvta.to.shared.u64 t, %1; cvt.u32.u64 %0, t; }" : "=r"(a) : "l"(p));
    return a;
}
__device__ __forceinline__ uint32_t f2tf32(float f) {
    uint32_t r;
    asm("cvt.rna.tf32.f32 %0, %1;" : "=r"(r) : "f"(f));
    return r;
}
#define CP_ASYNC16(saddr, gaddr) \
    asm volatile("cp.async.cg.shared.global [%0], [%1], 16;" :: "r"(saddr), "l"(gaddr))
#define CP_COMMIT()   asm volatile("cp.async.commit_group;" ::: "memory")
#define CP_WAIT(n)    asm volatile("cp.async.wait_group %0;" :: "n"(n) : "memory")

#define MMA_TF32(c, a, bf) \
    asm volatile("mma.sync.aligned.m16n8k8.row.col.f32.tf32.tf32.f32 " \
        "{%0,%1,%2,%3}, {%4,%5,%6,%7}, {%8,%9}, {%0,%1,%2,%3};" \
        : "+f"((c)[0]), "+f"((c)[1]), "+f"((c)[2]), "+f"((c)[3]) \
        : "r"((a)[0]), "r"((a)[1]), "r"((a)[2]), "r"((a)[3]), \
          "r"((bf)[0]), "r"((bf)[1]))

// ---------------- Kernel A: g[b,c] = sum_hw feats*preds ----
__global__ void gk_kernel(const float* __restrict__ feats,
                          const float* __restrict__ preds) {
    int c = blockIdx.x, b = blockIdx.y;
    const float* f  = feats + ((size_t)b * CIN + c) * HW;
    const float* pr = preds + (size_t)b * HW;
    int t = threadIdx.x;
    float s = 0.f;
#pragma unroll
    for (int i = t * 4; i < HW; i += 1024) {
        float4 fv = *(const float4*)(f + i);
        float4 pv = *(const float4*)(pr + i);
        s += fv.x * pv.x + fv.y * pv.y + fv.z * pv.z + fv.w * pv.w;
    }
    s = warp_sum(s);
    __shared__ float red[8];
    if ((t & 31) == 0) red[t >> 5] = s;
    __syncthreads();
    if (t == 0) {
        float tt = 0.f;
#pragma unroll
        for (int j = 0; j < 8; j++) tt += red[j];
        g_g[b * CIN + c] = tt;
    }
}

__global__ void predsum_kernel(const float* __restrict__ preds) {
    int b = blockIdx.x;
    const float* pr = preds + (size_t)b * HW;
    int t = threadIdx.x;
    float s = 0.f;
    for (int i = t; i < HW; i += 256) s += pr[i];
    s = warp_sum(s);
    __shared__ float red[8];
    if ((t & 31) == 0) red[t >> 5] = s;
    __syncthreads();
    if (t == 0) {
        float tt = 0.f;
#pragma unroll
        for (int j = 0; j < 8; j++) tt += red[j];
        g_predsum[b] = tt;
    }
}

__global__ void pooled_kernel(const float* __restrict__ W,
                              const float* __restrict__ bias) {
    __shared__ float gs[CIN];
    int b = blockIdx.x;
    int t = threadIdx.x;
    gs[t]       = g_g[b * CIN + t];
    gs[t + 256] = g_g[b * CIN + 256 + t];
    __syncthreads();
    const float* wr = W + (size_t)t * CIN;
    float s = 0.f;
#pragma unroll 8
    for (int c = 0; c < CIN; c++) s += wr[c] * gs[c];
    g_pooled[b * COUT + t] = (s + bias[t] * g_predsum[b]) * (1.0f / (float)HW);
}

// ---------------- Kernel C: sequential codebook scan ---------
__global__ void memscan_kernel(const int* __restrict__ epoch_p) {
    __shared__ float mem[32][COUT];
    __shared__ float x[COUT];
    __shared__ float sims[32];
    __shared__ float red[8];
    __shared__ float s_xnorm;
    __shared__ int   s_ptr, s_idx, s_ema;

    int t = threadIdx.x, lane = t & 31, w = t >> 5;
    if (t == 0) s_ptr = 0;
    float threshold = ((float)(*epoch_p) / 10.0f - 2.0f) * 0.4f / 13.0f + 0.3f;
    __syncthreads();

    for (int i = 0; i < BATCH; i++) {
        x[t] = g_pooled[i * COUT + t];
        __syncthreads();
        float v = x[t] * x[t];
        v = warp_sum(v);
        if (lane == 0) red[w] = v;
        __syncthreads();
        if (t == 0) {
            float s = 0.f;
#pragma unroll
            for (int j = 0; j < 8; j++) s += red[j];
            s_xnorm = sqrtf(s);
        }
        __syncthreads();
        int ptr = s_ptr;
        float xnorm = s_xnorm;
        for (int p = w; p < ptr; p += 8) {
            float dot = 0.f, nn = 0.f;
#pragma unroll
            for (int c = lane; c < COUT; c += 32) {
                float m = mem[p][c];
                dot += m * x[c];
                nn  += m * m;
            }
            dot = warp_sum(dot);
            nn  = warp_sum(nn);
            if (lane == 0) {
                float norm = sqrtf(nn);
                if (norm == 0.f) norm = 1.f;
                sims[p] = dot / (norm * xnorm);
            }
        }
        __syncthreads();
        if (t == 0) {
            int   idx  = 0;
            float best = -INFINITY;
            for (int p = 0; p < ptr; p++)
                if (sims[p] > best) { best = sims[p]; idx = p; }
            int ema = (ptr > 0) && (best >= threshold);
            s_ema = ema;
            s_idx = ema ? idx : ptr;
            if (!ema) s_ptr = ptr + 1;
        }
        __syncthreads();
        if (s_ema) mem[s_idx][t] = mem[s_idx][t] * 0.9f + 0.1f * x[t];
        else       mem[s_idx][t] = x[t];
        __syncthreads();
    }
    int ptr = s_ptr;
    for (int p = 0; p < ptr; p++) g_mem[p * COUT + t] = mem[p][t];
    if (t == 0) g_ptr = ptr;
}

// ---------------- Kernel D: proj GEMM via mma.sync tf32 ------------------
// out[b, m, n] = sum_k W[m,k]*feats[b,k,n] + bias[m]
__global__ __launch_bounds__(256, 1)
void proj_mma(const float* __restrict__ feats,
              const float* __restrict__ W,
              const float* __restrict__ bias,
              float* __restrict__ out) {
    extern __shared__ char smem[];
    float* As = (float*)smem;                       // [64][516] tf32-rounded
    float* Bs = (float*)(smem + A_BYTES);           // 4 stages [16][264]

    int t = threadIdx.x, wid = t >> 5, lane = t & 31;
    int g = lane >> 2, tg = lane & 3;
    int b  = blockIdx.z;
    int m0 = blockIdx.y * BM;
    int n0 = blockIdx.x * BN;
    int warp_m = (wid >> 2) * 32;      // 0 or 32
    int warp_n = (wid & 3) * 64;       // 0,64,128,192

    const float* fb = feats + (size_t)b * CIN * HW + n0;
    uint32_t sB = smem_u32(Bs);

    // ---- prologue: stage entire A slice (64 x 512) as tf32 ----
#pragma unroll
    for (int i = 0; i < 32; i++) {
        int c = t + i * 256;           // float4 chunk id, 8192 total
        int row = c >> 7, col4 = (c & 127) * 4;
        float4 v = *(const float4*)(W + (size_t)(m0 + row) * CIN + col4);
        uint4 u;
        u.x = f2tf32(v.x); u.y = f2tf32(v.y);
        u.z = f2tf32(v.z); u.w = f2tf32(v.w);
        *(uint4*)(As + row * A_STRIDE + col4) = u;
    }

    // ---- prologue: first NSTB-1 B stages via cp.async ----
#pragma unroll
    for (int s = 0; s < NSTB - 1; s++) {
#pragma unroll
        for (int i = 0; i < 4; i++) {
            int c = t + i * 256;       // 16B chunk id, 1024 total
            int row = c >> 6, col16 = c & 63;
            CP_ASYNC16(sB + s * B_STAGE_BYTES + row * (B_STRIDE * 4) + col16 * 16,
                       fb + (size_t)(s * BK + row) * HW + col16 * 4);
        }
        CP_COMMIT();
    }
    __syncthreads();   // A ready

    float acc[2][8][4];
#pragma unroll
    for (int mt = 0; mt < 2; mt++)
#pragma unroll
        for (int nt = 0; nt < 8; nt++)
#pragma unroll
            for (int q = 0; q < 4; q++) acc[mt][nt][q] = 0.f;

    for (int kt = 0; kt < NKT; kt++) {
        // issue tile kt+3
        if (kt + NSTB - 1 < NKT) {
            int s = (kt + NSTB - 1) & (NSTB - 1);
#pragma unroll
            for (int i = 0; i < 4; i++) {
                int c = t + i * 256;
                int row = c >> 6, col16 = c & 63;
                CP_ASYNC16(sB + s * B_STAGE_BYTES + row * (B_STRIDE * 4) + col16 * 16,
                           fb + (size_t)((kt + NSTB - 1) * BK + row) * HW + col16 * 4);
            }
        }
        CP_COMMIT();
        CP_WAIT(2);
        __syncthreads();

        const float* BsS = Bs + (kt & (NSTB - 1)) * (BK * B_STRIDE);
#pragma unroll
        for (int kk = 0; kk < 2; kk++) {
            uint32_t af[2][4];
#pragma unroll
            for (int mt = 0; mt < 2; mt++) {
                const float* ap = As + (size_t)(warp_m + mt * 16 + g) * A_STRIDE
                                  + kt * BK + kk * 8 + tg;
                af[mt][0] = __float_as_uint(ap[0]);
                af[mt][1] = __float_as_uint(ap[8 * A_STRIDE]);
                af[mt][2] = __float_as_uint(ap[4]);
                af[mt][3] = __float_as_uint(ap[8 * A_STRIDE + 4]);
            }
            uint32_t bf[8][2];
#pragma unroll
            for (int nt = 0; nt < 8; nt++) {
                const float* bp = BsS + (kk * 8 + tg) * B_STRIDE + warp_n + nt * 8 + g;
                bf[nt][0] = f2tf32(bp[0]);
                bf[nt][1] = f2tf32(bp[4 * B_STRIDE]);
            }
#pragma unroll
            for (int mt = 0; mt < 2; mt++)
#pragma unroll
                for (int nt = 0; nt < 8; nt++)
                    MMA_TF32(acc[mt][nt], af[mt], bf[nt]);
        }
        __syncthreads();
    }

    // ---- epilogue ----
#pragma unroll
    for (int mt = 0; mt < 2; mt++) {
        int m = m0 + warp_m + mt * 16 + g;
        float bv0 = bias[m], bv1 = bias[m + 8];
        float* rowp = out + ((size_t)b * (2 * COUT) + m) * HW + n0 + warp_n + 2 * tg;
#pragma unroll
        for (int nt = 0; nt < 8; nt++) {
            float2 v0 = make_float2(acc[mt][nt][0] + bv0, acc[mt][nt][1] + bv0);
            float2 v1 = make_float2(acc[mt][nt][2] + bv1, acc[mt][nt][3] + bv1);
            *(float2*)(rowp + nt * 8)            = v0;
            *(float2*)(rowp + nt * 8 + 8 * HW)   = v1;
        }
    }
}

// ---------------- Kernel E: memory cross-attention -----------------------
__global__ __launch_bounds__(256)
void attn_kernel(float* __restrict__ out) {
    extern __shared__ float sm[];
    float* memS = sm;                                     // [32][256]
    float (*sbuf)[128] = (float(*)[128])(sm + 32 * COUT); // [32][128]

    int b  = blockIdx.y;
    int l0 = blockIdx.x * 128;
    int t  = threadIdx.x;
    int ptr = g_ptr;

    for (int idx = t; idx < 32 * COUT; idx += 256) {
        int p = idx >> 8;
        memS[idx] = (p < ptr) ? g_mem[idx] : 0.f;
    }
    const float* proj = out + (size_t)b * (2 * COUT) * HW;
    float*       aug  = out + (size_t)b * (2 * COUT) * HW + (size_t)COUT * HW;

    int tl = t & 31;
    int tp = t >> 5;

    float acc[4][4];
#pragma unroll
    for (int i = 0; i < 4; i++)
#pragma unroll
        for (int j = 0; j < 4; j++) acc[i][j] = 0.f;
    __syncthreads();

    for (int c0 = 0; c0 < COUT; c0 += 32) {
#pragma unroll
        for (int i = 0; i < 4; i++) {
            int idx = t + i * 256;
            int r   = idx >> 5;
            int cc  = (idx & 31) * 4;
            *(float4*)&sbuf[r][cc] =
                *(const float4*)(proj + (size_t)(c0 + r) * HW + l0 + cc);
        }
        __syncthreads();
#pragma unroll
        for (int cc = 0; cc < 32; cc++) {
            float4 xv = *(const float4*)&sbuf[cc][tl * 4];
#pragma unroll
            for (int i = 0; i < 4; i++) {
                float mv = memS[(tp * 4 + i) * COUT + c0 + cc];
                acc[i][0] += mv * xv.x;
                acc[i][1] += mv * xv.y;
                acc[i][2] += mv * xv.z;
                acc[i][3] += mv * xv.w;
            }
        }
        __syncthreads();
    }
#pragma unroll
    for (int i = 0; i < 4; i++) {
        *(float4*)&sbuf[tp * 4 + i][tl * 4] =
            make_float4(acc[i][0], acc[i][1], acc[i][2], acc[i][3]);
    }
    __syncthreads();

    if (t < 128) {
        int l = t;
        float mx = -INFINITY;
        for (int p = 0; p < ptr; p++) mx = fmaxf(mx, sbuf[p][l]);
        float ssum = 0.f;
        for (int p = 0; p < ptr; p++) {
            float e = expf(sbuf[p][l] - mx);
            sbuf[p][l] = e;
            ssum += e;
        }
        float inv = 1.0f / ssum;
        for (int p = 0; p < ptr; p++) sbuf[p][l] *= inv;
    }
    __syncthreads();

    int cbase = tp * 32;
    for (int cb = 0; cb < 32; cb += 8) {
        float s[8][4];
#pragma unroll
        for (int q = 0; q < 8; q++)
#pragma unroll
            for (int j = 0; j < 4; j++) s[q][j] = 0.f;
        for (int p = 0; p < ptr; p++) {
            float4 xa = *(const float4*)&sbuf[p][tl * 4];
#pragma unroll
            for (int q = 0; q < 8; q++) {
                float mv = memS[p * COUT + cbase + cb + q];
                s[q][0] += mv * xa.x;
                s[q][1] += mv * xa.y;
                s[q][2] += mv * xa.z;
                s[q][3] += mv * xa.w;
            }
        }
#pragma unroll
        for (int q = 0; q < 8; q++) {
            *(float4*)(aug + (size_t)(cbase + cb + q) * HW + l0 + tl * 4) =
                make_float4(s[q][0], s[q][1], s[q][2], s[q][3]);
        }
    }
}

// ---------------- launch --------------------------------------------------
extern "C" void kernel_launch(void* const* d_in, const int* in_sizes, int n_in,
                              void* d_out, int out_size) {
    const float* feats = (const float*)d_in[0];
    const float* preds = (const float*)d_in[1];
    const float* W     = (const float*)d_in[2];
    const float* bias  = (const float*)d_in[3];
    const int*   epoch = (const int*)d_in[4];
    float* out = (float*)d_out;

    cudaFuncSetAttribute(proj_mma, cudaFuncAttributeMaxDynamicSharedMemorySize, SMEM_TOTAL);

    gk_kernel<<<dim3(CIN, BATCH), 256>>>(feats, preds);
    predsum_kernel<<<BATCH, 256>>>(preds);
    pooled_kernel<<<BATCH, 256>>>(W, bias);
    memscan_kernel<<<1, 256>>>(epoch);
    proj_mma<<<dim3(HW / BN, COUT / BM, BATCH), 256, SMEM_TOTAL>>>(feats, W, bias, out);
    attn_kernel<<<dim3(HW / 128, BATCH), 256, 49152>>>(out);
}